// round 1
// baseline (speedup 1.0000x reference)
#include <cuda_runtime.h>
#include <cuda_bf16.h>
#include <cstdint>

// Problem constants
#define BATCH 2
#define SEQ   2048
#define DIN   1024
#define DOUT  1024
#define NHEAD 16
#define HDIM  64
#define M_ROWS (BATCH * SEQ)          // 4096
#define QKV_COLS (3 * DOUT)           // 3072

// Scratch (device globals; no runtime allocation allowed)
__device__ float g_qkv[(size_t)M_ROWS * QKV_COLS];   // (B*T, 3*DOUT)
__device__ float g_y[(size_t)M_ROWS * DOUT];         // (B*T, DOUT) attention output

// ---------------------------------------------------------------------------
// SGEMM: C[M,N] = A[M,K] @ B[N,K]^T (+bias). Both A and B row-major,
// K-contiguous (NT layout). BM=BN=128, BK=8, 256 threads, 8x8 microtile.
// ---------------------------------------------------------------------------
template <bool BIAS>
__global__ __launch_bounds__(256) void sgemm_nt(
    const float* __restrict__ A, const float* __restrict__ B,
    const float* __restrict__ bias, float* __restrict__ C,
    int M, int N, int K)
{
    __shared__ float As[8][128];
    __shared__ float Bs[8][128];

    const int tid = threadIdx.x;
    const int tx = tid & 15;          // 0..15
    const int ty = tid >> 4;          // 0..15

    const int bn = blockIdx.x * 128;
    const int bm = blockIdx.y * 128;

    const float* Ab = A + (size_t)bm * K;
    const float* Bb = B + (size_t)bn * K;

    const int lrow = tid >> 1;        // 0..127
    const int lk   = (tid & 1) * 4;   // 0 or 4

    float acc[8][8];
#pragma unroll
    for (int i = 0; i < 8; i++)
#pragma unroll
        for (int j = 0; j < 8; j++) acc[i][j] = 0.f;

    for (int k0 = 0; k0 < K; k0 += 8) {
        float4 a4 = *(const float4*)(Ab + (size_t)lrow * K + k0 + lk);
        float4 b4 = *(const float4*)(Bb + (size_t)lrow * K + k0 + lk);
        As[lk + 0][lrow] = a4.x; As[lk + 1][lrow] = a4.y;
        As[lk + 2][lrow] = a4.z; As[lk + 3][lrow] = a4.w;
        Bs[lk + 0][lrow] = b4.x; Bs[lk + 1][lrow] = b4.y;
        Bs[lk + 2][lrow] = b4.z; Bs[lk + 3][lrow] = b4.w;
        __syncthreads();

#pragma unroll
        for (int kk = 0; kk < 8; kk++) {
            float4 a0 = *(const float4*)&As[kk][ty * 8];
            float4 a1 = *(const float4*)&As[kk][ty * 8 + 4];
            float4 b0 = *(const float4*)&Bs[kk][tx * 8];
            float4 b1 = *(const float4*)&Bs[kk][tx * 8 + 4];
            float a[8] = {a0.x, a0.y, a0.z, a0.w, a1.x, a1.y, a1.z, a1.w};
            float b[8] = {b0.x, b0.y, b0.z, b0.w, b1.x, b1.y, b1.z, b1.w};
#pragma unroll
            for (int i = 0; i < 8; i++)
#pragma unroll
                for (int j = 0; j < 8; j++)
                    acc[i][j] = fmaf(a[i], b[j], acc[i][j]);
        }
        __syncthreads();
    }

#pragma unroll
    for (int i = 0; i < 8; i++) {
        int row = bm + ty * 8 + i;
        float* Cr = C + (size_t)row * N + bn + tx * 8;
#pragma unroll
        for (int j = 0; j < 8; j++) {
            float v = acc[i][j];
            if (BIAS) v += bias[bn + tx * 8 + j];
            Cr[j] = v;
        }
    }
}

// ---------------------------------------------------------------------------
// Flash attention (causal). One block per (q-tile of 64 rows, b*h).
// 256 threads arranged 16x16; each thread owns a 4x4 tile of S/O.
// SMEM (dynamic): Qs[64][65] (d-major), Ks[64][65] (d-major),
//                 Ps[64][65] (k-major), Vs[64][64] (token-major).
// ---------------------------------------------------------------------------
#define FLASH_SMEM_FLOATS (3 * 64 * 65 + 64 * 64)
#define FLASH_SMEM_BYTES  (FLASH_SMEM_FLOATS * 4)

__global__ __launch_bounds__(256) void flash_kernel(
    const float* __restrict__ qkv, float* __restrict__ y)
{
    extern __shared__ float sm[];
    float (*Qs)[65] = (float(*)[65])sm;                 // [d][r]
    float (*Ks)[65] = (float(*)[65])(sm + 64 * 65);     // [d][c]
    float (*Ps)[65] = (float(*)[65])(sm + 2 * 64 * 65); // [k][r]
    float (*Vs)[64] = (float(*)[64])(sm + 3 * 64 * 65); // [k][d]

    const int qi = blockIdx.x;        // q tile index (0..31)
    const int bh = blockIdx.y;        // 0..31
    const int b  = bh >> 4;
    const int h  = bh & 15;

    const float* base = qkv + (size_t)b * SEQ * QKV_COLS;
    const int hoff = h * HDIM;

    const int tid = threadIdx.x;
    const int tx = tid & 15;
    const int ty = tid >> 4;

    // Load Q tile transposed: Qs[d][r]
    for (int idx = tid; idx < 64 * 16; idx += 256) {
        int r = idx >> 4;
        int d4 = (idx & 15) * 4;
        float4 v = *(const float4*)(base + (size_t)(qi * 64 + r) * QKV_COLS + hoff + d4);
        Qs[d4 + 0][r] = v.x; Qs[d4 + 1][r] = v.y;
        Qs[d4 + 2][r] = v.z; Qs[d4 + 3][r] = v.w;
    }

    float m[4], l[4], O[4][4];
#pragma unroll
    for (int i = 0; i < 4; i++) {
        m[i] = -1e30f; l[i] = 0.f;
#pragma unroll
        for (int j = 0; j < 4; j++) O[i][j] = 0.f;
    }

    const float scale = 0.125f;  // 1/sqrt(64)

    for (int jt = 0; jt <= qi; jt++) {
        __syncthreads();  // previous iteration's P@V done; safe to overwrite K/V

        // Load K transposed (Ks[d][c]) and V direct (Vs[c][d])
        for (int idx = tid; idx < 64 * 16; idx += 256) {
            int c = idx >> 4;
            int d4 = (idx & 15) * 4;
            const float* rowp = base + (size_t)(jt * 64 + c) * QKV_COLS + hoff;
            float4 kv = *(const float4*)(rowp + DOUT + d4);
            Ks[d4 + 0][c] = kv.x; Ks[d4 + 1][c] = kv.y;
            Ks[d4 + 2][c] = kv.z; Ks[d4 + 3][c] = kv.w;
            float4 vv = *(const float4*)(rowp + 2 * DOUT + d4);
            *(float4*)&Vs[c][d4] = vv;
        }
        __syncthreads();

        // S = Q @ K^T (4x4 per thread)
        float s[4][4];
#pragma unroll
        for (int i = 0; i < 4; i++)
#pragma unroll
            for (int j = 0; j < 4; j++) s[i][j] = 0.f;

        for (int d = 0; d < 64; d++) {
            float a[4], bb[4];
#pragma unroll
            for (int i = 0; i < 4; i++) a[i] = Qs[d][ty * 4 + i];
#pragma unroll
            for (int j = 0; j < 4; j++) bb[j] = Ks[d][tx * 4 + j];
#pragma unroll
            for (int i = 0; i < 4; i++)
#pragma unroll
                for (int j = 0; j < 4; j++)
                    s[i][j] = fmaf(a[i], bb[j], s[i][j]);
        }

        // scale + causal mask (diagonal tile only)
#pragma unroll
        for (int i = 0; i < 4; i++)
#pragma unroll
            for (int j = 0; j < 4; j++) {
                s[i][j] *= scale;
                if (jt == qi && (tx * 4 + j) > (ty * 4 + i)) s[i][j] = -1e30f;
            }

        // online softmax per row (reduce across the 16 tx lanes)
#pragma unroll
        for (int i = 0; i < 4; i++) {
            float rm = fmaxf(fmaxf(s[i][0], s[i][1]), fmaxf(s[i][2], s[i][3]));
#pragma unroll
            for (int off = 8; off >= 1; off >>= 1)
                rm = fmaxf(rm, __shfl_xor_sync(0xffffffffu, rm, off));
            float mn = fmaxf(m[i], rm);
            float corr = __expf(m[i] - mn);
            l[i] *= corr;
#pragma unroll
            for (int j = 0; j < 4; j++) O[i][j] *= corr;
            float rs = 0.f;
#pragma unroll
            for (int j = 0; j < 4; j++) {
                float p = __expf(s[i][j] - mn);
                s[i][j] = p;
                rs += p;
            }
#pragma unroll
            for (int off = 8; off >= 1; off >>= 1)
                rs += __shfl_xor_sync(0xffffffffu, rs, off);
            l[i] += rs;
            m[i] = mn;
        }

        // store P transposed: Ps[k][r], k = score column
#pragma unroll
        for (int i = 0; i < 4; i++)
#pragma unroll
            for (int j = 0; j < 4; j++)
                Ps[tx * 4 + j][ty * 4 + i] = s[i][j];
        __syncthreads();

        // O += P @ V
        for (int k = 0; k < 64; k++) {
            float a[4], bb[4];
#pragma unroll
            for (int i = 0; i < 4; i++) a[i] = Ps[k][ty * 4 + i];
#pragma unroll
            for (int j = 0; j < 4; j++) bb[j] = Vs[k][tx * 4 + j];
#pragma unroll
            for (int i = 0; i < 4; i++)
#pragma unroll
                for (int j = 0; j < 4; j++)
                    O[i][j] = fmaf(a[i], bb[j], O[i][j]);
        }
    }

    // write y[b][t][h*64 + c] = O / l
#pragma unroll
    for (int i = 0; i < 4; i++) {
        int t = qi * 64 + ty * 4 + i;
        float inv = 1.0f / l[i];
        float* yr = y + (size_t)b * SEQ * DOUT + (size_t)t * DOUT + hoff + tx * 4;
#pragma unroll
        for (int j = 0; j < 4; j++) yr[j] = O[i][j] * inv;
    }
}

// ---------------------------------------------------------------------------
extern "C" void kernel_launch(void* const* d_in, const int* in_sizes, int n_in,
                              void* d_out, int out_size)
{
    const float* x     = (const float*)d_in[0];  // (2,2048,1024)
    const float* w_qkv = (const float*)d_in[1];  // (3072,1024)
    const float* w_out = (const float*)d_in[2];  // (1024,1024)
    const float* b_out = (const float*)d_in[3];  // (1024,)
    float* out = (float*)d_out;

    float* qkv_ptr; float* y_ptr;
    cudaGetSymbolAddress((void**)&qkv_ptr, g_qkv);
    cudaGetSymbolAddress((void**)&y_ptr, g_y);

    // 1) QKV projection: (4096,1024) @ (3072,1024)^T -> (4096,3072)
    sgemm_nt<false><<<dim3(QKV_COLS / 128, M_ROWS / 128), 256>>>(
        x, w_qkv, nullptr, qkv_ptr, M_ROWS, QKV_COLS, DIN);

    // 2) Flash attention
    cudaFuncSetAttribute(flash_kernel,
                         cudaFuncAttributeMaxDynamicSharedMemorySize,
                         FLASH_SMEM_BYTES);
    flash_kernel<<<dim3(SEQ / 64, BATCH * NHEAD), 256, FLASH_SMEM_BYTES>>>(
        qkv_ptr, y_ptr);

    // 3) Output projection + bias: (4096,1024) @ (1024,1024)^T + b
    sgemm_nt<true><<<dim3(DOUT / 128, M_ROWS / 128), 256>>>(
        y_ptr, w_out, b_out, out, M_ROWS, DOUT, DOUT);
}

// round 2
// speedup vs baseline: 1.7061x; 1.7061x over previous
#include <cuda_runtime.h>
#include <cuda_bf16.h>
#include <cstdint>

// Problem constants
#define BATCH 2
#define SEQ   2048
#define DIN   1024
#define DOUT  1024
#define NHEAD 16
#define HDIM  64
#define M_ROWS (BATCH * SEQ)          // 4096
#define QKV_COLS (3 * DOUT)           // 3072

// Scratch (device globals; no runtime allocation allowed)
__device__ float g_qkv[(size_t)M_ROWS * QKV_COLS];   // (B*T, 3*DOUT)
__device__ float g_y[(size_t)M_ROWS * DOUT];         // (B*T, DOUT)

// ---------------------------------------------------------------------------
// TF32 tensor-core GEMM: C[M,N] = A[M,K] @ B[N,K]^T (+bias)
// A, B row-major, K-contiguous (NT). BM=BN=128, BK=16, 256 threads (8 warps),
// warp tile 64x32 via mma.sync.m16n8k8.tf32. cp.async double-buffered SMEM.
// SMEM layout [row][k] with row stride 20 floats: fragment loads hit
// bank (20*g + t) mod 32, injective for g in 0..7, t in 0..3 -> conflict-free.
// ---------------------------------------------------------------------------
#define BM 128
#define BN 128
#define BK 16
#define LDS_STRIDE 20   // BK + 4 pad

__device__ __forceinline__ void cp_async16(void* smem, const void* gmem) {
    uint32_t s = (uint32_t)__cvta_generic_to_shared(smem);
    asm volatile("cp.async.cg.shared.global [%0], [%1], 16;\n" :: "r"(s), "l"(gmem));
}
__device__ __forceinline__ void cp_commit() {
    asm volatile("cp.async.commit_group;\n");
}
template <int N>
__device__ __forceinline__ void cp_wait() {
    asm volatile("cp.async.wait_group %0;\n" :: "n"(N));
}
__device__ __forceinline__ uint32_t f2tf(float f) {
    uint32_t r;
    asm("cvt.rna.tf32.f32 %0, %1;" : "=r"(r) : "f"(f));
    return r;
}
__device__ __forceinline__ void mma_tf32(float c[4],
                                         const uint32_t a[4],
                                         const uint32_t b[2]) {
    asm volatile(
        "mma.sync.aligned.m16n8k8.row.col.f32.tf32.tf32.f32 "
        "{%0,%1,%2,%3}, {%4,%5,%6,%7}, {%8,%9}, {%0,%1,%2,%3};\n"
        : "+f"(c[0]), "+f"(c[1]), "+f"(c[2]), "+f"(c[3])
        : "r"(a[0]), "r"(a[1]), "r"(a[2]), "r"(a[3]), "r"(b[0]), "r"(b[1]));
}

template <bool BIAS>
__global__ __launch_bounds__(256, 2) void gemm_tf32_nt(
    const float* __restrict__ A, const float* __restrict__ B,
    const float* __restrict__ bias, float* __restrict__ C,
    int M, int N, int K)
{
    __shared__ float As[2][BM][LDS_STRIDE];
    __shared__ float Bs[2][BN][LDS_STRIDE];

    const int tid  = threadIdx.x;
    const int lane = tid & 31;
    const int warp = tid >> 5;
    const int wm = warp & 1;          // 2 warps along M (64 rows each)
    const int wn = warp >> 1;         // 4 warps along N (32 cols each)
    const int g  = lane >> 2;         // group id 0..7
    const int tg = lane & 3;          // thread-in-group 0..3

    const int bm = blockIdx.y * BM;
    const int bn = blockIdx.x * BN;

    // Global->SMEM: each thread copies 2 float4 from A tile and 2 from B tile.
    const int ldr = tid >> 2;          // 0..63
    const int ldc = (tid & 3) * 4;     // 0,4,8,12

    const float* Ag0 = A + (size_t)(bm + ldr) * K + ldc;
    const float* Ag1 = A + (size_t)(bm + ldr + 64) * K + ldc;
    const float* Bg0 = B + (size_t)(bn + ldr) * K + ldc;
    const float* Bg1 = B + (size_t)(bn + ldr + 64) * K + ldc;

    float acc[4][4][4];
#pragma unroll
    for (int mt = 0; mt < 4; mt++)
#pragma unroll
        for (int nt = 0; nt < 4; nt++)
#pragma unroll
            for (int i = 0; i < 4; i++) acc[mt][nt][i] = 0.f;

    const int nstages = K / BK;

    // prefetch stage 0
    cp_async16(&As[0][ldr][ldc],      Ag0);
    cp_async16(&As[0][ldr + 64][ldc], Ag1);
    cp_async16(&Bs[0][ldr][ldc],      Bg0);
    cp_async16(&Bs[0][ldr + 64][ldc], Bg1);
    cp_commit();

    for (int it = 0; it < nstages; it++) {
        const int buf = it & 1;
        if (it + 1 < nstages) {
            const int nb = (it + 1) & 1;
            const int ko = (it + 1) * BK;
            cp_async16(&As[nb][ldr][ldc],      Ag0 + ko);
            cp_async16(&As[nb][ldr + 64][ldc], Ag1 + ko);
            cp_async16(&Bs[nb][ldr][ldc],      Bg0 + ko);
            cp_async16(&Bs[nb][ldr + 64][ldc], Bg1 + ko);
            cp_commit();
            cp_wait<1>();
        } else {
            cp_wait<0>();
        }
        __syncthreads();

#pragma unroll
        for (int ks = 0; ks < BK; ks += 8) {
            uint32_t af[4][4], bf[4][2];
#pragma unroll
            for (int mt = 0; mt < 4; mt++) {
                const int m = wm * 64 + mt * 16;
                af[mt][0] = f2tf(As[buf][m + g][ks + tg]);
                af[mt][1] = f2tf(As[buf][m + g + 8][ks + tg]);
                af[mt][2] = f2tf(As[buf][m + g][ks + tg + 4]);
                af[mt][3] = f2tf(As[buf][m + g + 8][ks + tg + 4]);
            }
#pragma unroll
            for (int nt = 0; nt < 4; nt++) {
                const int n = wn * 32 + nt * 8;
                bf[nt][0] = f2tf(Bs[buf][n + g][ks + tg]);
                bf[nt][1] = f2tf(Bs[buf][n + g][ks + tg + 4]);
            }
#pragma unroll
            for (int mt = 0; mt < 4; mt++)
#pragma unroll
                for (int nt = 0; nt < 4; nt++)
                    mma_tf32(acc[mt][nt], af[mt], bf[nt]);
        }
        __syncthreads();
    }

    // Epilogue. c0:(g, 2tg) c1:(g, 2tg+1) c2:(g+8, 2tg) c3:(g+8, 2tg+1)
#pragma unroll
    for (int mt = 0; mt < 4; mt++) {
        const int row0 = bm + wm * 64 + mt * 16 + g;
#pragma unroll
        for (int nt = 0; nt < 4; nt++) {
            const int col = bn + wn * 32 + nt * 8 + 2 * tg;
            float b0 = 0.f, b1 = 0.f;
            if (BIAS) { b0 = bias[col]; b1 = bias[col + 1]; }
            float2 v0 = make_float2(acc[mt][nt][0] + b0, acc[mt][nt][1] + b1);
            float2 v1 = make_float2(acc[mt][nt][2] + b0, acc[mt][nt][3] + b1);
            *(float2*)(C + (size_t)row0 * N + col) = v0;
            *(float2*)(C + (size_t)(row0 + 8) * N + col) = v1;
        }
    }
}

// ---------------------------------------------------------------------------
// Flash attention (causal) - unchanged fp32 version from round 1.
// ---------------------------------------------------------------------------
#define FLASH_SMEM_FLOATS (3 * 64 * 65 + 64 * 64)
#define FLASH_SMEM_BYTES  (FLASH_SMEM_FLOATS * 4)

__global__ __launch_bounds__(256) void flash_kernel(
    const float* __restrict__ qkv, float* __restrict__ y)
{
    extern __shared__ float sm[];
    float (*Qs)[65] = (float(*)[65])sm;                 // [d][r]
    float (*Ks)[65] = (float(*)[65])(sm + 64 * 65);     // [d][c]
    float (*Ps)[65] = (float(*)[65])(sm + 2 * 64 * 65); // [k][r]
    float (*Vs)[64] = (float(*)[64])(sm + 3 * 64 * 65); // [k][d]

    const int qi = blockIdx.x;
    const int bh = blockIdx.y;
    const int b  = bh >> 4;
    const int h  = bh & 15;

    const float* base = qkv + (size_t)b * SEQ * QKV_COLS;
    const int hoff = h * HDIM;

    const int tid = threadIdx.x;
    const int tx = tid & 15;
    const int ty = tid >> 4;

    for (int idx = tid; idx < 64 * 16; idx += 256) {
        int r = idx >> 4;
        int d4 = (idx & 15) * 4;
        float4 v = *(const float4*)(base + (size_t)(qi * 64 + r) * QKV_COLS + hoff + d4);
        Qs[d4 + 0][r] = v.x; Qs[d4 + 1][r] = v.y;
        Qs[d4 + 2][r] = v.z; Qs[d4 + 3][r] = v.w;
    }

    float m[4], l[4], O[4][4];
#pragma unroll
    for (int i = 0; i < 4; i++) {
        m[i] = -1e30f; l[i] = 0.f;
#pragma unroll
        for (int j = 0; j < 4; j++) O[i][j] = 0.f;
    }

    const float scale = 0.125f;

    for (int jt = 0; jt <= qi; jt++) {
        __syncthreads();

        for (int idx = tid; idx < 64 * 16; idx += 256) {
            int c = idx >> 4;
            int d4 = (idx & 15) * 4;
            const float* rowp = base + (size_t)(jt * 64 + c) * QKV_COLS + hoff;
            float4 kv = *(const float4*)(rowp + DOUT + d4);
            Ks[d4 + 0][c] = kv.x; Ks[d4 + 1][c] = kv.y;
            Ks[d4 + 2][c] = kv.z; Ks[d4 + 3][c] = kv.w;
            float4 vv = *(const float4*)(rowp + 2 * DOUT + d4);
            *(float4*)&Vs[c][d4] = vv;
        }
        __syncthreads();

        float s[4][4];
#pragma unroll
        for (int i = 0; i < 4; i++)
#pragma unroll
            for (int j = 0; j < 4; j++) s[i][j] = 0.f;

        for (int d = 0; d < 64; d++) {
            float a[4], bb[4];
#pragma unroll
            for (int i = 0; i < 4; i++) a[i] = Qs[d][ty * 4 + i];
#pragma unroll
            for (int j = 0; j < 4; j++) bb[j] = Ks[d][tx * 4 + j];
#pragma unroll
            for (int i = 0; i < 4; i++)
#pragma unroll
                for (int j = 0; j < 4; j++)
                    s[i][j] = fmaf(a[i], bb[j], s[i][j]);
        }

#pragma unroll
        for (int i = 0; i < 4; i++)
#pragma unroll
            for (int j = 0; j < 4; j++) {
                s[i][j] *= scale;
                if (jt == qi && (tx * 4 + j) > (ty * 4 + i)) s[i][j] = -1e30f;
            }

#pragma unroll
        for (int i = 0; i < 4; i++) {
            float rm = fmaxf(fmaxf(s[i][0], s[i][1]), fmaxf(s[i][2], s[i][3]));
#pragma unroll
            for (int off = 8; off >= 1; off >>= 1)
                rm = fmaxf(rm, __shfl_xor_sync(0xffffffffu, rm, off));
            float mn = fmaxf(m[i], rm);
            float corr = __expf(m[i] - mn);
            l[i] *= corr;
#pragma unroll
            for (int j = 0; j < 4; j++) O[i][j] *= corr;
            float rs = 0.f;
#pragma unroll
            for (int j = 0; j < 4; j++) {
                float p = __expf(s[i][j] - mn);
                s[i][j] = p;
                rs += p;
            }
#pragma unroll
            for (int off = 8; off >= 1; off >>= 1)
                rs += __shfl_xor_sync(0xffffffffu, rs, off);
            l[i] += rs;
            m[i] = mn;
        }

#pragma unroll
        for (int i = 0; i < 4; i++)
#pragma unroll
            for (int j = 0; j < 4; j++)
                Ps[tx * 4 + j][ty * 4 + i] = s[i][j];
        __syncthreads();

        for (int k = 0; k < 64; k++) {
            float a[4], bb[4];
#pragma unroll
            for (int i = 0; i < 4; i++) a[i] = Ps[k][ty * 4 + i];
#pragma unroll
            for (int j = 0; j < 4; j++) bb[j] = Vs[k][tx * 4 + j];
#pragma unroll
            for (int i = 0; i < 4; i++)
#pragma unroll
                for (int j = 0; j < 4; j++)
                    O[i][j] = fmaf(a[i], bb[j], O[i][j]);
        }
    }

#pragma unroll
    for (int i = 0; i < 4; i++) {
        int t = qi * 64 + ty * 4 + i;
        float inv = 1.0f / l[i];
        float* yr = y + (size_t)b * SEQ * DOUT + (size_t)t * DOUT + hoff + tx * 4;
#pragma unroll
        for (int j = 0; j < 4; j++) yr[j] = O[i][j] * inv;
    }
}

// ---------------------------------------------------------------------------
extern "C" void kernel_launch(void* const* d_in, const int* in_sizes, int n_in,
                              void* d_out, int out_size)
{
    const float* x     = (const float*)d_in[0];  // (2,2048,1024)
    const float* w_qkv = (const float*)d_in[1];  // (3072,1024)
    const float* w_out = (const float*)d_in[2];  // (1024,1024)
    const float* b_out = (const float*)d_in[3];  // (1024,)
    float* out = (float*)d_out;

    float* qkv_ptr; float* y_ptr;
    cudaGetSymbolAddress((void**)&qkv_ptr, g_qkv);
    cudaGetSymbolAddress((void**)&y_ptr, g_y);

    // 1) QKV projection: (4096,1024) @ (3072,1024)^T -> (4096,3072)
    gemm_tf32_nt<false><<<dim3(QKV_COLS / BN, M_ROWS / BM), 256>>>(
        x, w_qkv, nullptr, qkv_ptr, M_ROWS, QKV_COLS, DIN);

    // 2) Flash attention
    cudaFuncSetAttribute(flash_kernel,
                         cudaFuncAttributeMaxDynamicSharedMemorySize,
                         FLASH_SMEM_BYTES);
    flash_kernel<<<dim3(SEQ / 64, BATCH * NHEAD), 256, FLASH_SMEM_BYTES>>>(
        qkv_ptr, y_ptr);

    // 3) Output projection + bias: (4096,1024) @ (1024,1024)^T + b
    gemm_tf32_nt<true><<<dim3(DOUT / BN, M_ROWS / BM), 256>>>(
        y_ptr, w_out, b_out, out, M_ROWS, DOUT, DOUT);
}

// round 3
// speedup vs baseline: 3.3388x; 1.9570x over previous
#include <cuda_runtime.h>
#include <cuda_bf16.h>
#include <cstdint>

// Problem constants
#define BATCH 2
#define SEQ   2048
#define DIN   1024
#define DOUT  1024
#define NHEAD 16
#define HDIM  64
#define M_ROWS (BATCH * SEQ)          // 4096
#define QKV_COLS (3 * DOUT)           // 3072

// Scratch (device globals; no runtime allocation allowed)
__device__ float g_qkv[(size_t)M_ROWS * QKV_COLS];   // (B*T, 3*DOUT)
__device__ float g_y[(size_t)M_ROWS * DOUT];         // (B*T, DOUT)

// ---------------------------------------------------------------------------
// Shared PTX helpers
// ---------------------------------------------------------------------------
__device__ __forceinline__ void cp_async16(void* smem, const void* gmem) {
    uint32_t s = (uint32_t)__cvta_generic_to_shared(smem);
    asm volatile("cp.async.cg.shared.global [%0], [%1], 16;\n" :: "r"(s), "l"(gmem));
}
__device__ __forceinline__ void cp_commit() {
    asm volatile("cp.async.commit_group;\n");
}
template <int N>
__device__ __forceinline__ void cp_wait() {
    asm volatile("cp.async.wait_group %0;\n" :: "n"(N));
}
__device__ __forceinline__ uint32_t f2tf(float f) {
    uint32_t r;
    asm("cvt.rna.tf32.f32 %0, %1;" : "=r"(r) : "f"(f));
    return r;
}
__device__ __forceinline__ void mma_tf32(float c[4],
                                         const uint32_t a[4],
                                         const uint32_t b[2]) {
    asm volatile(
        "mma.sync.aligned.m16n8k8.row.col.f32.tf32.tf32.f32 "
        "{%0,%1,%2,%3}, {%4,%5,%6,%7}, {%8,%9}, {%0,%1,%2,%3};\n"
        : "+f"(c[0]), "+f"(c[1]), "+f"(c[2]), "+f"(c[3])
        : "r"(a[0]), "r"(a[1]), "r"(a[2]), "r"(a[3]), "r"(b[0]), "r"(b[1]));
}

// ---------------------------------------------------------------------------
// TF32 tensor-core GEMM: C[M,N] = A[M,K] @ B[N,K]^T (+bias)  (round-2, kept)
// ---------------------------------------------------------------------------
#define BM 128
#define BN 128
#define BK 16
#define LDS_STRIDE 20   // BK + 4 pad

template <bool BIAS>
__global__ __launch_bounds__(256, 2) void gemm_tf32_nt(
    const float* __restrict__ A, const float* __restrict__ B,
    const float* __restrict__ bias, float* __restrict__ C,
    int M, int N, int K)
{
    __shared__ float As[2][BM][LDS_STRIDE];
    __shared__ float Bs[2][BN][LDS_STRIDE];

    const int tid  = threadIdx.x;
    const int lane = tid & 31;
    const int warp = tid >> 5;
    const int wm = warp & 1;
    const int wn = warp >> 1;
    const int g  = lane >> 2;
    const int tg = lane & 3;

    const int bm = blockIdx.y * BM;
    const int bn = blockIdx.x * BN;

    const int ldr = tid >> 2;
    const int ldc = (tid & 3) * 4;

    const float* Ag0 = A + (size_t)(bm + ldr) * K + ldc;
    const float* Ag1 = A + (size_t)(bm + ldr + 64) * K + ldc;
    const float* Bg0 = B + (size_t)(bn + ldr) * K + ldc;
    const float* Bg1 = B + (size_t)(bn + ldr + 64) * K + ldc;

    float acc[4][4][4];
#pragma unroll
    for (int mt = 0; mt < 4; mt++)
#pragma unroll
        for (int nt = 0; nt < 4; nt++)
#pragma unroll
            for (int i = 0; i < 4; i++) acc[mt][nt][i] = 0.f;

    const int nstages = K / BK;

    cp_async16(&As[0][ldr][ldc],      Ag0);
    cp_async16(&As[0][ldr + 64][ldc], Ag1);
    cp_async16(&Bs[0][ldr][ldc],      Bg0);
    cp_async16(&Bs[0][ldr + 64][ldc], Bg1);
    cp_commit();

    for (int it = 0; it < nstages; it++) {
        const int buf = it & 1;
        if (it + 1 < nstages) {
            const int nb = (it + 1) & 1;
            const int ko = (it + 1) * BK;
            cp_async16(&As[nb][ldr][ldc],      Ag0 + ko);
            cp_async16(&As[nb][ldr + 64][ldc], Ag1 + ko);
            cp_async16(&Bs[nb][ldr][ldc],      Bg0 + ko);
            cp_async16(&Bs[nb][ldr + 64][ldc], Bg1 + ko);
            cp_commit();
            cp_wait<1>();
        } else {
            cp_wait<0>();
        }
        __syncthreads();

#pragma unroll
        for (int ks = 0; ks < BK; ks += 8) {
            uint32_t af[4][4], bf[4][2];
#pragma unroll
            for (int mt = 0; mt < 4; mt++) {
                const int m = wm * 64 + mt * 16;
                af[mt][0] = f2tf(As[buf][m + g][ks + tg]);
                af[mt][1] = f2tf(As[buf][m + g + 8][ks + tg]);
                af[mt][2] = f2tf(As[buf][m + g][ks + tg + 4]);
                af[mt][3] = f2tf(As[buf][m + g + 8][ks + tg + 4]);
            }
#pragma unroll
            for (int nt = 0; nt < 4; nt++) {
                const int n = wn * 32 + nt * 8;
                bf[nt][0] = f2tf(Bs[buf][n + g][ks + tg]);
                bf[nt][1] = f2tf(Bs[buf][n + g][ks + tg + 4]);
            }
#pragma unroll
            for (int mt = 0; mt < 4; mt++)
#pragma unroll
                for (int nt = 0; nt < 4; nt++)
                    mma_tf32(acc[mt][nt], af[mt], bf[nt]);
        }
        __syncthreads();
    }

#pragma unroll
    for (int mt = 0; mt < 4; mt++) {
        const int row0 = bm + wm * 64 + mt * 16 + g;
#pragma unroll
        for (int nt = 0; nt < 4; nt++) {
            const int col = bn + wn * 32 + nt * 8 + 2 * tg;
            float b0 = 0.f, b1 = 0.f;
            if (BIAS) { b0 = bias[col]; b1 = bias[col + 1]; }
            float2 v0 = make_float2(acc[mt][nt][0] + b0, acc[mt][nt][1] + b1);
            float2 v1 = make_float2(acc[mt][nt][2] + b0, acc[mt][nt][3] + b1);
            *(float2*)(C + (size_t)row0 * N + col) = v0;
            *(float2*)(C + (size_t)(row0 + 8) * N + col) = v1;
        }
    }
}

// ---------------------------------------------------------------------------
// Flash attention (causal) with tf32 mma.
// Block: 128 q-rows, 8 warps (16 rows each). Iterate 64-wide kv tiles.
// SMEM: Ks[2][64][68]  (K rows, stride 68 == 4 mod 32 -> conflict-free bf)
//       Vs[2][64][72]  (V rows, stride 72 == 8 mod 32 -> conflict-free bf)
//       Ps[128][68]    (P staging, warp-private rows; also Q staging at start)
// Scale 1/8 and log2(e) folded into Q; softmax in base-2 (exp2f == MUFU EX2).
// ---------------------------------------------------------------------------
#define KS_ST 68
#define VS_ST 72
#define FLASH_SMEM_BYTES ((2*64*KS_ST + 2*64*VS_ST + 128*KS_ST) * 4)

__global__ __launch_bounds__(256, 1) void flash_mma_kernel(
    const float* __restrict__ qkv, float* __restrict__ y)
{
    extern __shared__ float sm[];
    float (*Ks)[64][KS_ST] = (float(*)[64][KS_ST])sm;
    float (*Vs)[64][VS_ST] = (float(*)[64][VS_ST])(sm + 2 * 64 * KS_ST);
    float (*Ps)[KS_ST]     = (float(*)[KS_ST])(sm + 2 * 64 * KS_ST + 2 * 64 * VS_ST);

    const int qi = (int)gridDim.x - 1 - (int)blockIdx.x;  // heavy tiles first
    const int bh = blockIdx.y;
    const int b  = bh >> 4;
    const int h  = bh & 15;
    const int qbase = qi * 128;

    const float* base = qkv + (size_t)b * SEQ * QKV_COLS;
    const int hoff = h * HDIM;

    const int tid  = threadIdx.x;
    const int lane = tid & 31;
    const int warp = tid >> 5;
    const int g  = lane >> 2;
    const int tg = lane & 3;
    const int w16 = warp * 16;

    // --- stage Q tile into Ps area, then build per-warp tf32 A-fragments ---
    for (int i = tid; i < 128 * 16; i += 256) {
        int r  = i >> 4;
        int c4 = (i & 15) * 4;
        float4 v = *(const float4*)(base + (size_t)(qbase + r) * QKV_COLS + hoff + c4);
        *(float4*)&Ps[r][c4] = v;
    }
    __syncthreads();

    const float qscale = 0.125f * 1.4426950408889634f;  // 1/sqrt(64) * log2(e)
    uint32_t aq[8][4];
#pragma unroll
    for (int ks = 0; ks < 8; ks++) {
        aq[ks][0] = f2tf(qscale * Ps[w16 + g][ks * 8 + tg]);
        aq[ks][1] = f2tf(qscale * Ps[w16 + g + 8][ks * 8 + tg]);
        aq[ks][2] = f2tf(qscale * Ps[w16 + g][ks * 8 + tg + 4]);
        aq[ks][3] = f2tf(qscale * Ps[w16 + g + 8][ks * 8 + tg + 4]);
    }
    __syncthreads();

    float O[8][4];
#pragma unroll
    for (int n = 0; n < 8; n++)
#pragma unroll
        for (int i = 0; i < 4; i++) O[n][i] = 0.f;
    float m0 = -1e30f, m1 = -1e30f, l0 = 0.f, l1 = 0.f;

    const int njt = 2 * (qi + 1);

    // K/V tile prefetch (64 rows x 64 floats each)
    auto prefetch = [&](int jt, int buf) {
        const int jb = jt * 64;
        for (int i = tid; i < 64 * 16; i += 256) {
            int r  = i >> 4;
            int c4 = (i & 15) * 4;
            const float* rowp = base + (size_t)(jb + r) * QKV_COLS + hoff;
            cp_async16(&Ks[buf][r][c4], rowp + DOUT + c4);
            cp_async16(&Vs[buf][r][c4], rowp + 2 * DOUT + c4);
        }
        cp_commit();
    };

    prefetch(0, 0);

    for (int jt = 0; jt < njt; jt++) {
        const int buf = jt & 1;
        if (jt + 1 < njt) {
            prefetch(jt + 1, (jt + 1) & 1);
            cp_wait<1>();
        } else {
            cp_wait<0>();
        }
        __syncthreads();

        // ---- S = Qhat @ K^T (128x64 per block, 16x64 per warp) ----
        float S[8][4];
#pragma unroll
        for (int n = 0; n < 8; n++)
#pragma unroll
            for (int i = 0; i < 4; i++) S[n][i] = 0.f;

#pragma unroll
        for (int ks = 0; ks < 8; ks++) {
#pragma unroll
            for (int n = 0; n < 8; n++) {
                uint32_t kb[2];
                kb[0] = f2tf(Ks[buf][n * 8 + g][ks * 8 + tg]);
                kb[1] = f2tf(Ks[buf][n * 8 + g][ks * 8 + tg + 4]);
                mma_tf32(S[n], aq[ks], kb);
            }
        }

        // ---- causal mask (only possible on last two kv tiles) ----
        if (jt >= 2 * qi) {
            const int r0 = qbase + w16 + g;
            const int r1 = r0 + 8;
            const int cb = jt * 64 + 2 * tg;
#pragma unroll
            for (int n = 0; n < 8; n++) {
                const int c0 = cb + n * 8;
                if (c0 > r0)     S[n][0] = -1e30f;
                if (c0 + 1 > r0) S[n][1] = -1e30f;
                if (c0 > r1)     S[n][2] = -1e30f;
                if (c0 + 1 > r1) S[n][3] = -1e30f;
            }
        }

        // ---- online softmax (base-2), rows g and g+8 ----
        float rm0 = -1e30f, rm1 = -1e30f;
#pragma unroll
        for (int n = 0; n < 8; n++) {
            rm0 = fmaxf(rm0, fmaxf(S[n][0], S[n][1]));
            rm1 = fmaxf(rm1, fmaxf(S[n][2], S[n][3]));
        }
        rm0 = fmaxf(rm0, __shfl_xor_sync(0xffffffffu, rm0, 1));
        rm0 = fmaxf(rm0, __shfl_xor_sync(0xffffffffu, rm0, 2));
        rm1 = fmaxf(rm1, __shfl_xor_sync(0xffffffffu, rm1, 1));
        rm1 = fmaxf(rm1, __shfl_xor_sync(0xffffffffu, rm1, 2));

        const float mn0 = fmaxf(m0, rm0);
        const float mn1 = fmaxf(m1, rm1);
        const float corr0 = exp2f(m0 - mn0);
        const float corr1 = exp2f(m1 - mn1);
        m0 = mn0; m1 = mn1;

        float rs0 = 0.f, rs1 = 0.f;
#pragma unroll
        for (int n = 0; n < 8; n++) {
            float p0 = exp2f(S[n][0] - mn0);
            float p1 = exp2f(S[n][1] - mn0);
            float p2 = exp2f(S[n][2] - mn1);
            float p3 = exp2f(S[n][3] - mn1);
            rs0 += p0 + p1;
            rs1 += p2 + p3;
            O[n][0] *= corr0; O[n][1] *= corr0;
            O[n][2] *= corr1; O[n][3] *= corr1;
            // stage P (warp-private rows)
            *(float2*)&Ps[w16 + g][n * 8 + 2 * tg]     = make_float2(p0, p1);
            *(float2*)&Ps[w16 + g + 8][n * 8 + 2 * tg] = make_float2(p2, p3);
        }
        rs0 += __shfl_xor_sync(0xffffffffu, rs0, 1);
        rs0 += __shfl_xor_sync(0xffffffffu, rs0, 2);
        rs1 += __shfl_xor_sync(0xffffffffu, rs1, 1);
        rs1 += __shfl_xor_sync(0xffffffffu, rs1, 2);
        l0 = l0 * corr0 + rs0;
        l1 = l1 * corr1 + rs1;

        __syncwarp();

        // ---- O += P @ V ----
#pragma unroll
        for (int ks = 0; ks < 8; ks++) {
            uint32_t pa[4];
            pa[0] = f2tf(Ps[w16 + g][ks * 8 + tg]);
            pa[1] = f2tf(Ps[w16 + g + 8][ks * 8 + tg]);
            pa[2] = f2tf(Ps[w16 + g][ks * 8 + tg + 4]);
            pa[3] = f2tf(Ps[w16 + g + 8][ks * 8 + tg + 4]);
#pragma unroll
            for (int n = 0; n < 8; n++) {
                uint32_t vb[2];
                vb[0] = f2tf(Vs[buf][ks * 8 + tg][n * 8 + g]);
                vb[1] = f2tf(Vs[buf][ks * 8 + tg + 4][n * 8 + g]);
                mma_tf32(O[n], pa, vb);
            }
        }
        __syncthreads();   // all warps done with buf before it is refilled
    }

    // ---- epilogue: y = O / l ----
    const float inv0 = 1.0f / l0;
    const float inv1 = 1.0f / l1;
    const int r0 = qbase + w16 + g;
    float* yr0 = y + (size_t)b * SEQ * DOUT + (size_t)r0 * DOUT + hoff;
    float* yr1 = yr0 + 8 * DOUT;
#pragma unroll
    for (int n = 0; n < 8; n++) {
        const int c = n * 8 + 2 * tg;
        *(float2*)(yr0 + c) = make_float2(O[n][0] * inv0, O[n][1] * inv0);
        *(float2*)(yr1 + c) = make_float2(O[n][2] * inv1, O[n][3] * inv1);
    }
}

// ---------------------------------------------------------------------------
extern "C" void kernel_launch(void* const* d_in, const int* in_sizes, int n_in,
                              void* d_out, int out_size)
{
    const float* x     = (const float*)d_in[0];  // (2,2048,1024)
    const float* w_qkv = (const float*)d_in[1];  // (3072,1024)
    const float* w_out = (const float*)d_in[2];  // (1024,1024)
    const float* b_out = (const float*)d_in[3];  // (1024,)
    float* out = (float*)d_out;

    float* qkv_ptr; float* y_ptr;
    cudaGetSymbolAddress((void**)&qkv_ptr, g_qkv);
    cudaGetSymbolAddress((void**)&y_ptr, g_y);

    // 1) QKV projection: (4096,1024) @ (3072,1024)^T -> (4096,3072)
    gemm_tf32_nt<false><<<dim3(QKV_COLS / BN, M_ROWS / BM), 256>>>(
        x, w_qkv, nullptr, qkv_ptr, M_ROWS, QKV_COLS, DIN);

    // 2) Flash attention (tf32 mma)
    cudaFuncSetAttribute(flash_mma_kernel,
                         cudaFuncAttributeMaxDynamicSharedMemorySize,
                         FLASH_SMEM_BYTES);
    flash_mma_kernel<<<dim3(SEQ / 128, BATCH * NHEAD), 256, FLASH_SMEM_BYTES>>>(
        qkv_ptr, y_ptr);

    // 3) Output projection + bias: (4096,1024) @ (1024,1024)^T + b
    gemm_tf32_nt<true><<<dim3(DOUT / BN, M_ROWS / BM), 256>>>(
        y_ptr, w_out, b_out, out, M_ROWS, DOUT, DOUT);
}